// round 5
// baseline (speedup 1.0000x reference)
#include <cuda_runtime.h>
#include <cstdint>

#define OUTF 11008
#define INF  4096
#define BATCH 8
#define NKC 8                        // K chunks (split-K factor)
#define KCHUNK (INF / NKC)           // 512 columns per chunk
#define GRIDX 74                     // CTAs per K-chunk; 74*8 = 592 = 148 SMs * 4 CTAs
#define NTILES (OUTF / 32)           // 344 row tiles of 32 rows
#define CTA_THREADS 128

// Swizzle: inject byte-offset bits [9:7] (== lane bits [2:0] on the compute
// path) into bank bits [6:4]. Makes compute LDS.128 conflict-free within each
// lane octet (4-phase floor).
#define SWZ(a) ((a) ^ ((((a) >> 7) & 7) << 4))

// Packed f32x2 ops (Blackwell sm_103a).
__device__ __forceinline__ float2 ffma2(float2 a, float2 b, float2 c) {
    float2 d;
    asm("{\n\t.reg .b64 A,B,C,D;\n\t"
        "mov.b64 A,{%2,%3};\n\tmov.b64 B,{%4,%5};\n\tmov.b64 C,{%6,%7};\n\t"
        "fma.rn.f32x2 D,A,B,C;\n\tmov.b64 {%0,%1},D;\n\t}"
        : "=f"(d.x), "=f"(d.y)
        : "f"(a.x), "f"(a.y), "f"(b.x), "f"(b.y), "f"(c.x), "f"(c.y));
    return d;
}
__device__ __forceinline__ float2 fadd2(float2 a, float2 b) {
    float2 d;
    asm("{\n\t.reg .b64 A,B,D;\n\t"
        "mov.b64 A,{%2,%3};\n\tmov.b64 B,{%4,%5};\n\t"
        "add.rn.f32x2 D,A,B;\n\tmov.b64 {%0,%1},D;\n\t}"
        : "=f"(d.x), "=f"(d.y) : "f"(a.x), "f"(a.y), "f"(b.x), "f"(b.y));
    return d;
}
__device__ __forceinline__ float2 fmul2(float2 a, float2 b) {
    float2 d;
    asm("{\n\t.reg .b64 A,B,D;\n\t"
        "mov.b64 A,{%2,%3};\n\tmov.b64 B,{%4,%5};\n\t"
        "mul.rn.f32x2 D,A,B;\n\tmov.b64 {%0,%1},D;\n\t}"
        : "=f"(d.x), "=f"(d.y) : "f"(a.x), "f"(a.y), "f"(b.x), "f"(b.y));
    return d;
}

__device__ __forceinline__ float4 ldx(const char* xs, int col, int half) {
    int off = (col << 5) + (half << 4);
    off = SWZ(off);
    return *(const float4*)(xs + off);
}

__global__ void zero_kernel(float* __restrict__ out, int n) {
    int i = blockIdx.x * blockDim.x + threadIdx.x;
    if (i < n) out[i] = 0.0f;
}

__global__ __launch_bounds__(CTA_THREADS, 4)
void qlin_kernel(const float* __restrict__ x,
                 const int*   __restrict__ packed,
                 const float* __restrict__ scales,
                 float*       __restrict__ out) {
    // x chunk in smem, [col][batch] layout (32B per column), SWZ-swizzled. 16 KB.
    __shared__ __align__(16) float xs_f[KCHUNK * BATCH];
    char* xs = (char*)xs_f;

    const int tid   = threadIdx.x;
    const int lane  = tid & 31;
    const int warp  = tid >> 5;
    const int kbase = blockIdx.y * KCHUNK;

    // ── Fill x chunk ONCE per CTA. Warp w loads rows {2w, 2w+1}; 16 lanes per
    // row give coalesced LDG.128 (256B/row run).
    {
        const int r = 2 * warp + (lane >> 4);
        const int c4b = lane & 15;
        const float* xrow = x + (size_t)r * INF + kbase;
        #pragma unroll
        for (int p = 0; p < 8; p++) {
            const int c = 4 * (c4b + 16 * p);
            float4 v = *(const float4*)(xrow + c);
            #pragma unroll
            for (int k = 0; k < 4; k++) {
                int off = ((c + k) << 5) + (r << 2);
                off = SWZ(off);
                *(float*)(xs + off) = (&v.x)[k];
            }
        }
    }
    __syncthreads();

    const int g = lane >> 3;   // which of the 4 q4-blocks in a 128-col t-step

    // ── Persistent loop over row tiles (4-5 per CTA; one wave total).
    for (int rt = blockIdx.x; rt < NTILES; rt += GRIDX) {
        const int rowbase = rt * 32 + warp * 8;
        const int*   pbase = packed + (size_t)rowbase * (INF / 2) + (kbase >> 1) + 2 * lane;
        const float* sbase = scales + (size_t)rowbase * (INF / 32) + (kbase >> 5);

        float2 acc[8][4];   // [row][batch-pair]
        #pragma unroll
        for (int i = 0; i < 8; i++)
            #pragma unroll
            for (int p = 0; p < 4; p++) acc[i][p] = make_float2(0.f, 0.f);

        const float2 m8 = make_float2(-8388616.0f, -8388616.0f);  // -(2^23+8)

        #pragma unroll
        for (int t = 0; t < 4; t++) {      // 128 cols per t-step
            // W: coalesced LDG.64, lane owns int2 -> cols [128t+4*lane, +4)
            int2 w2[8];
            #pragma unroll
            for (int i = 0; i < 8; i++)
                w2[i] = *(const int2*)(pbase + (size_t)i * (INF / 2) + 64 * t);

            // Scales: warp-uniform broadcast LDG.128 (4 block scales), then select.
            float s[8];
            #pragma unroll
            for (int i = 0; i < 8; i++) {
                float4 sf = *(const float4*)(sbase + (size_t)i * (INF / 32) + 4 * t);
                float se = (g & 1) ? sf.y : sf.x;
                float so = (g & 1) ? sf.w : sf.z;
                s[i] = (g & 2) ? so : se;
            }

            #pragma unroll
            for (int e = 0; e < 2; e++) {
                const int c0 = 128 * t + 4 * lane + 2 * e;   // cols c0, c0+1
                float4 xa0 = ldx(xs, c0,     0);  // col c0,   batches 0-3
                float4 xb0 = ldx(xs, c0,     1);  // col c0,   batches 4-7
                float4 xa1 = ldx(xs, c0 + 1, 0);
                float4 xb1 = ldx(xs, c0 + 1, 1);

                #pragma unroll
                for (int i = 0; i < 8; i++) {
                    const int v = e ? w2[i].y : w2[i].x;   // byte value 0..255
                    // magic-mantissa: float(0x4B000000|n) = 2^23+n exactly;
                    // (2^23+n)-(2^23+8) = n-8 exactly (Sterbenz); one rounding in mul.
                    const int lob = (v & 15) | 0x4B000000;
                    const int hib = ((v >> 4) & 15) | 0x4B000000;
                    float2 q  = fadd2(make_float2(__int_as_float(lob), __int_as_float(hib)), m8);
                    float2 wv = fmul2(q, make_float2(s[i], s[i]));  // (w_c0, w_c1)

                    float2 wl = make_float2(wv.x, wv.x);
                    float2 wh = make_float2(wv.y, wv.y);
                    acc[i][0] = ffma2(wl, make_float2(xa0.x, xa0.y), acc[i][0]);
                    acc[i][1] = ffma2(wl, make_float2(xa0.z, xa0.w), acc[i][1]);
                    acc[i][2] = ffma2(wl, make_float2(xb0.x, xb0.y), acc[i][2]);
                    acc[i][3] = ffma2(wl, make_float2(xb0.z, xb0.w), acc[i][3]);
                    acc[i][0] = ffma2(wh, make_float2(xa1.x, xa1.y), acc[i][0]);
                    acc[i][1] = ffma2(wh, make_float2(xa1.z, xa1.w), acc[i][1]);
                    acc[i][2] = ffma2(wh, make_float2(xb1.x, xb1.y), acc[i][2]);
                    acc[i][3] = ffma2(wh, make_float2(xb1.z, xb1.w), acc[i][3]);
                }
            }
        }

        // ── Cross-lane reduction (lanes cover disjoint K columns) + atomics.
        #pragma unroll
        for (int i = 0; i < 8; i++) {
            #pragma unroll
            for (int p = 0; p < 4; p++) {
                float2 vv = acc[i][p];
                #pragma unroll
                for (int m = 16; m > 0; m >>= 1) {
                    vv.x += __shfl_xor_sync(0xFFFFFFFF, vv.x, m);
                    vv.y += __shfl_xor_sync(0xFFFFFFFF, vv.y, m);
                }
                if (lane == 0) {
                    const int row = rowbase + i;
                    atomicAdd(&out[(size_t)(2 * p)     * OUTF + row], vv.x);
                    atomicAdd(&out[(size_t)(2 * p + 1) * OUTF + row], vv.y);
                }
            }
        }
    }
}

extern "C" void kernel_launch(void* const* d_in, const int* in_sizes, int n_in,
                              void* d_out, int out_size) {
    const float* x      = (const float*)d_in[0];
    const int*   packed = (const int*)d_in[1];
    const float* scales = (const float*)d_in[2];
    float*       out    = (float*)d_out;

    zero_kernel<<<(out_size + 255) / 256, 256>>>(out, out_size);

    dim3 grid(GRIDX, NKC);   // (74, 8) = 592 CTAs = one full wave at 4 CTAs/SM
    qlin_kernel<<<grid, CTA_THREADS>>>(x, packed, scales, out);
}

// round 6
// speedup vs baseline: 1.0101x; 1.0101x over previous
#include <cuda_runtime.h>
#include <cstdint>

#define OUTF 11008
#define INF  4096
#define BATCH 8
#define NKC 8                        // K chunks (split-K factor)
#define KCHUNK (INF / NKC)           // 512 columns per chunk
#define GRIDX 74                     // CTAs per K-chunk; 74*8 = 592 = 148 SMs * 4 CTAs
#define NTILES (OUTF / 32)           // 344 row tiles of 32 rows
#define CTA_THREADS 128

// Swizzle: inject byte-offset bits [9:7] (== lane bits [2:0] on the compute
// path) into bank bits [6:4]. Makes compute LDS.128 conflict-free within each
// lane octet (4-phase floor).
#define SWZ(a) ((a) ^ ((((a) >> 7) & 7) << 4))

// Packed f32x2 ops (Blackwell sm_103a).
__device__ __forceinline__ float2 ffma2(float2 a, float2 b, float2 c) {
    float2 d;
    asm("{\n\t.reg .b64 A,B,C,D;\n\t"
        "mov.b64 A,{%2,%3};\n\tmov.b64 B,{%4,%5};\n\tmov.b64 C,{%6,%7};\n\t"
        "fma.rn.f32x2 D,A,B,C;\n\tmov.b64 {%0,%1},D;\n\t}"
        : "=f"(d.x), "=f"(d.y)
        : "f"(a.x), "f"(a.y), "f"(b.x), "f"(b.y), "f"(c.x), "f"(c.y));
    return d;
}
__device__ __forceinline__ float2 fadd2(float2 a, float2 b) {
    float2 d;
    asm("{\n\t.reg .b64 A,B,D;\n\t"
        "mov.b64 A,{%2,%3};\n\tmov.b64 B,{%4,%5};\n\t"
        "add.rn.f32x2 D,A,B;\n\tmov.b64 {%0,%1},D;\n\t}"
        : "=f"(d.x), "=f"(d.y) : "f"(a.x), "f"(a.y), "f"(b.x), "f"(b.y));
    return d;
}
__device__ __forceinline__ float2 fmul2(float2 a, float2 b) {
    float2 d;
    asm("{\n\t.reg .b64 A,B,D;\n\t"
        "mov.b64 A,{%2,%3};\n\tmov.b64 B,{%4,%5};\n\t"
        "mul.rn.f32x2 D,A,B;\n\tmov.b64 {%0,%1},D;\n\t}"
        : "=f"(d.x), "=f"(d.y) : "f"(a.x), "f"(a.y), "f"(b.x), "f"(b.y));
    return d;
}

__device__ __forceinline__ float4 ldx(const char* xs, int col, int half) {
    int off = (col << 5) + (half << 4);
    off = SWZ(off);
    return *(const float4*)(xs + off);
}

__global__ void zero_kernel(float* __restrict__ out, int n) {
    int i = blockIdx.x * blockDim.x + threadIdx.x;
    if (i < n) out[i] = 0.0f;
}

__global__ __launch_bounds__(CTA_THREADS, 4)
void qlin_kernel(const float* __restrict__ x,
                 const int*   __restrict__ packed,
                 const float* __restrict__ scales,
                 float*       __restrict__ out) {
    // x chunk in smem, [col][batch] layout (32B per column), SWZ-swizzled. 16 KB.
    __shared__ __align__(16) float xs_f[KCHUNK * BATCH];
    char* xs = (char*)xs_f;

    const int tid   = threadIdx.x;
    const int lane  = tid & 31;
    const int warp  = tid >> 5;
    const int kbase = blockIdx.y * KCHUNK;

    // ── Fill x chunk ONCE per CTA. Warp w loads rows {2w, 2w+1}; 16 lanes per
    // row give coalesced LDG.128 (256B/row run).
    {
        const int r = 2 * warp + (lane >> 4);
        const int c4b = lane & 15;
        const float* xrow = x + (size_t)r * INF + kbase;
        #pragma unroll
        for (int p = 0; p < 8; p++) {
            const int c = 4 * (c4b + 16 * p);
            float4 v = *(const float4*)(xrow + c);
            #pragma unroll
            for (int k = 0; k < 4; k++) {
                int off = ((c + k) << 5) + (r << 2);
                off = SWZ(off);
                *(float*)(xs + off) = (&v.x)[k];
            }
        }
    }
    __syncthreads();

    const int g = lane >> 3;   // which of the 4 q4-blocks in a 128-col t-step

    // ── Persistent loop over row tiles (4-5 per CTA; one wave total).
    for (int rt = blockIdx.x; rt < NTILES; rt += GRIDX) {
        const int rowbase = rt * 32 + warp * 8;
        const int*   pbase = packed + (size_t)rowbase * (INF / 2) + (kbase >> 1) + 2 * lane;
        const float* sbase = scales + (size_t)rowbase * (INF / 32) + (kbase >> 5);

        float2 acc[8][4];   // [row][batch-pair]
        #pragma unroll
        for (int i = 0; i < 8; i++)
            #pragma unroll
            for (int p = 0; p < 4; p++) acc[i][p] = make_float2(0.f, 0.f);

        const float2 m8 = make_float2(-8388616.0f, -8388616.0f);  // -(2^23+8)

        #pragma unroll
        for (int t = 0; t < 4; t++) {      // 128 cols per t-step
            // W: coalesced LDG.64, lane owns int2 -> cols [128t+4*lane, +4)
            int2 w2[8];
            #pragma unroll
            for (int i = 0; i < 8; i++)
                w2[i] = *(const int2*)(pbase + (size_t)i * (INF / 2) + 64 * t);

            // Scales: warp-uniform broadcast LDG.128 (4 block scales), then select.
            float s[8];
            #pragma unroll
            for (int i = 0; i < 8; i++) {
                float4 sf = *(const float4*)(sbase + (size_t)i * (INF / 32) + 4 * t);
                float se = (g & 1) ? sf.y : sf.x;
                float so = (g & 1) ? sf.w : sf.z;
                s[i] = (g & 2) ? so : se;
            }

            #pragma unroll
            for (int e = 0; e < 2; e++) {
                const int c0 = 128 * t + 4 * lane + 2 * e;   // cols c0, c0+1
                float4 xa0 = ldx(xs, c0,     0);  // col c0,   batches 0-3
                float4 xb0 = ldx(xs, c0,     1);  // col c0,   batches 4-7
                float4 xa1 = ldx(xs, c0 + 1, 0);
                float4 xb1 = ldx(xs, c0 + 1, 1);

                #pragma unroll
                for (int i = 0; i < 8; i++) {
                    const int v = e ? w2[i].y : w2[i].x;   // byte value 0..255
                    // magic-mantissa: float(0x4B000000|n) = 2^23+n exactly;
                    // (2^23+n)-(2^23+8) = n-8 exactly (Sterbenz); one rounding in mul.
                    const int lob = (v & 15) | 0x4B000000;
                    const int hib = ((v >> 4) & 15) | 0x4B000000;
                    float2 q  = fadd2(make_float2(__int_as_float(lob), __int_as_float(hib)), m8);
                    float2 wv = fmul2(q, make_float2(s[i], s[i]));  // (w_c0, w_c1)

                    float2 wl = make_float2(wv.x, wv.x);
                    float2 wh = make_float2(wv.y, wv.y);
                    acc[i][0] = ffma2(wl, make_float2(xa0.x, xa0.y), acc[i][0]);
                    acc[i][1] = ffma2(wl, make_float2(xa0.z, xa0.w), acc[i][1]);
                    acc[i][2] = ffma2(wl, make_float2(xb0.x, xb0.y), acc[i][2]);
                    acc[i][3] = ffma2(wl, make_float2(xb0.z, xb0.w), acc[i][3]);
                    acc[i][0] = ffma2(wh, make_float2(xa1.x, xa1.y), acc[i][0]);
                    acc[i][1] = ffma2(wh, make_float2(xa1.z, xa1.w), acc[i][1]);
                    acc[i][2] = ffma2(wh, make_float2(xb1.x, xb1.y), acc[i][2]);
                    acc[i][3] = ffma2(wh, make_float2(xb1.z, xb1.w), acc[i][3]);
                }
            }
        }

        // ── Cross-lane reduction (lanes cover disjoint K columns) + atomics.
        #pragma unroll
        for (int i = 0; i < 8; i++) {
            #pragma unroll
            for (int p = 0; p < 4; p++) {
                float2 vv = acc[i][p];
                #pragma unroll
                for (int m = 16; m > 0; m >>= 1) {
                    vv.x += __shfl_xor_sync(0xFFFFFFFF, vv.x, m);
                    vv.y += __shfl_xor_sync(0xFFFFFFFF, vv.y, m);
                }
                if (lane == 0) {
                    const int row = rowbase + i;
                    atomicAdd(&out[(size_t)(2 * p)     * OUTF + row], vv.x);
                    atomicAdd(&out[(size_t)(2 * p + 1) * OUTF + row], vv.y);
                }
            }
        }
    }
}

extern "C" void kernel_launch(void* const* d_in, const int* in_sizes, int n_in,
                              void* d_out, int out_size) {
    const float* x      = (const float*)d_in[0];
    const int*   packed = (const int*)d_in[1];
    const float* scales = (const float*)d_in[2];
    float*       out    = (float*)d_out;

    zero_kernel<<<(out_size + 255) / 256, 256>>>(out, out_size);

    dim3 grid(GRIDX, NKC);   // (74, 8) = 592 CTAs = one full wave at 4 CTAs/SM
    qlin_kernel<<<grid, CTA_THREADS>>>(x, packed, scales, out);
}

// round 7
// speedup vs baseline: 2.4120x; 2.3878x over previous
#include <cuda_runtime.h>
#include <cuda_fp16.h>
#include <cstdint>

#define OUTF 11008
#define INF  4096
#define ROWS 64
#define KCTA 128
#define GRID_X (OUTF / ROWS)   // 172
#define GRID_Y (INF / KCTA)    // 32

// x pre-split to fp16 hi/lo, layout [k2][batch] as half2-in-unsigned:
// g_XH[k2*8 + n] = half2( x[n][2*k2], x[n][2*k2+1] ) rounded; g_XL = residual.
__device__ __align__(16) unsigned g_XH[(INF / 2) * 8];
__device__ __align__(16) unsigned g_XL[(INF / 2) * 8];

__global__ void zero_kernel(float* __restrict__ out, int n) {
    int i = blockIdx.x * blockDim.x + threadIdx.x;
    if (i < n) out[i] = 0.0f;
}

__global__ void prep_x(const float* __restrict__ x) {
    int i = blockIdx.x * blockDim.x + threadIdx.x;
    if (i >= (INF / 2) * 8) return;
    int k2 = i >> 3, n = i & 7;
    float f0 = x[n * INF + 2 * k2];
    float f1 = x[n * INF + 2 * k2 + 1];
    __half h0 = __float2half_rn(f0), h1 = __float2half_rn(f1);
    __half l0 = __float2half_rn(f0 - __half2float(h0));
    __half l1 = __float2half_rn(f1 - __half2float(h1));
    __half2 H = __halves2half2(h0, h1), L = __halves2half2(l0, l1);
    g_XH[i] = *reinterpret_cast<unsigned*>(&H);
    g_XL[i] = *reinterpret_cast<unsigned*>(&L);
}

// Dequant one packed byte (one int32, two nibbles) -> half2 (n_lo-8, n_hi-8).
// fp16(0x6400|n) = 1024+n exactly; (1024+n) - 1032 = n-8 exactly (Sterbenz).
__device__ __forceinline__ unsigned dq(unsigned v) {
    unsigned t = ((v | (v << 12)) & 0x000F000Fu) | 0x64006400u;
    unsigned c = 0xE408E408u;  // half2(-1032, -1032)
    __half2 h = __hadd2(*reinterpret_cast<__half2*>(&t),
                        *reinterpret_cast<__half2*>(&c));
    return *reinterpret_cast<unsigned*>(&h);
}

__device__ __forceinline__ void mma16816(float& d0, float& d1, float& d2, float& d3,
                                         unsigned a0, unsigned a1, unsigned a2, unsigned a3,
                                         unsigned b0, unsigned b1) {
    asm volatile(
        "mma.sync.aligned.m16n8k16.row.col.f32.f16.f16.f32 "
        "{%0,%1,%2,%3},{%4,%5,%6,%7},{%8,%9},{%0,%1,%2,%3};"
        : "+f"(d0), "+f"(d1), "+f"(d2), "+f"(d3)
        : "r"(a0), "r"(a1), "r"(a2), "r"(a3), "r"(b0), "r"(b1));
}

__global__ __launch_bounds__(128, 8)
void qlin_kernel(const int*   __restrict__ packed,
                 const float* __restrict__ scales,
                 float*       __restrict__ out) {
    // Raw packed W words, row stride 68 -> A-frag LDS banks (4*gid + tg) bijective.
    __shared__ __align__(16) unsigned Wsm[ROWS * 68];   // 17408 B
    __shared__ __align__(16) unsigned xhs[64 * 8];      // 2048 B (64 k2 x 8 batch)
    __shared__ __align__(16) unsigned xls[64 * 8];      // 2048 B
    __shared__ float ssm[ROWS * 5];                     // 1280 B (stride 5: conflict-free)

    const int tid  = threadIdx.x;
    const int lane = tid & 31, warp = tid >> 5;
    const int gid  = lane >> 2, tg = lane & 3;
    const int rowbase = blockIdx.x * ROWS;
    const int kbase   = blockIdx.y * KCTA;

    // ── x fill: 512 words per array = 128 int4; one int4 per thread per array.
    {
        const int4* gh = reinterpret_cast<const int4*>(g_XH + (kbase >> 1) * 8);
        const int4* gl = reinterpret_cast<const int4*>(g_XL + (kbase >> 1) * 8);
        reinterpret_cast<int4*>(xhs)[tid] = gh[tid];
        reinterpret_cast<int4*>(xls)[tid] = gl[tid];
    }
    // ── scales fill: 64 rows x 4 blocks (f32, kept f32 for exact dequant).
    if (tid < ROWS) {
        float4 s4 = *reinterpret_cast<const float4*>(
            scales + (size_t)(rowbase + tid) * (INF / 32) + (kbase >> 5));
        ssm[tid * 5 + 0] = s4.x; ssm[tid * 5 + 1] = s4.y;
        ssm[tid * 5 + 2] = s4.z; ssm[tid * 5 + 3] = s4.w;
    }
    // ── W fill: 64 rows x 64 words; coalesced LDG.128 (256B contiguous per row).
    {
        const int kb2 = kbase >> 1;
        #pragma unroll
        for (int p = 0; p < 8; p++) {
            int idx = p * 128 + tid;
            int row = idx >> 4, q = idx & 15;
            int4 v = *reinterpret_cast<const int4*>(
                packed + (size_t)(rowbase + row) * (INF / 2) + kb2 + q * 4);
            *reinterpret_cast<int4*>(&Wsm[row * 68 + q * 4]) = v;
        }
    }
    __syncthreads();

    const int r0 = warp * 16 + gid;
    const unsigned* wr0 = &Wsm[r0 * 68];
    const unsigned* wr8 = wr0 + 8 * 68;

    float acc0 = 0.f, acc1 = 0.f, acc2 = 0.f, acc3 = 0.f;

    #pragma unroll
    for (int blk = 0; blk < 4; blk++) {       // one q4 block = 32 cols = 2 k-tiles
        float t0 = 0.f, t1 = 0.f, t2 = 0.f, t3 = 0.f;
        #pragma unroll
        for (int u = 0; u < 2; u++) {
            const int t = blk * 2 + u;        // k-tile (16 cols)
            const int j = 8 * t + tg;         // word index: byte j -> cols (2j, 2j+1)
            // A frags: exact integer (n-8) fp16.
            unsigned a0 = dq(wr0[j]);
            unsigned a1 = dq(wr8[j]);
            unsigned a2 = dq(wr0[j + 4]);
            unsigned a3 = dq(wr8[j + 4]);
            // B frags: x hi and lo, conflict-free LDS.32.
            unsigned bh0 = xhs[j * 8 + gid];
            unsigned bh1 = xhs[(j + 4) * 8 + gid];
            unsigned bl0 = xls[j * 8 + gid];
            unsigned bl1 = xls[(j + 4) * 8 + gid];
            mma16816(t0, t1, t2, t3, a0, a1, a2, a3, bh0, bh1);
            mma16816(t0, t1, t2, t3, a0, a1, a2, a3, bl0, bl1);
        }
        // Per-block f32 scale applied to the block partial (weights stay exact).
        float s0 = ssm[r0 * 5 + blk];
        float s8 = ssm[(r0 + 8) * 5 + blk];
        acc0 = fmaf(s0, t0, acc0);
        acc1 = fmaf(s0, t1, acc1);
        acc2 = fmaf(s8, t2, acc2);
        acc3 = fmaf(s8, t3, acc3);
    }

    // ── Epilogue: D frag -> out[batch][row], 4 atomics per lane, no reduction.
    const int gr0 = rowbase + r0, gr8 = gr0 + 8;
    atomicAdd(&out[(size_t)(2 * tg)     * OUTF + gr0], acc0);
    atomicAdd(&out[(size_t)(2 * tg + 1) * OUTF + gr0], acc1);
    atomicAdd(&out[(size_t)(2 * tg)     * OUTF + gr8], acc2);
    atomicAdd(&out[(size_t)(2 * tg + 1) * OUTF + gr8], acc3);
}

extern "C" void kernel_launch(void* const* d_in, const int* in_sizes, int n_in,
                              void* d_out, int out_size) {
    const float* x      = (const float*)d_in[0];
    const int*   packed = (const int*)d_in[1];
    const float* scales = (const float*)d_in[2];
    float*       out    = (float*)d_out;

    zero_kernel<<<(out_size + 255) / 256, 256>>>(out, out_size);
    prep_x<<<((INF / 2) * 8 + 255) / 256, 256>>>(x);

    dim3 grid(GRID_X, GRID_Y);   // (172, 32) = 5504 CTAs, 8/SM
    qlin_kernel<<<grid, 128>>>(packed, scales, out);
}

// round 8
// speedup vs baseline: 2.9455x; 1.2212x over previous
#include <cuda_runtime.h>
#include <cuda_fp16.h>
#include <cstdint>

#define OUTF 11008
#define INF  4096
#define ROWS 64
#define KCTA 256
#define WSTRIDE 132                    // 128 words + 4 pad: banks (4*gid+tg+8t), bijective
#define GRID_X (OUTF / ROWS)           // 172
#define GRID_Y (INF / KCTA)            // 16

// x pre-split to fp16 hi/lo, layout [k2][batch] as half2-in-unsigned.
__device__ __align__(16) unsigned g_XH[(INF / 2) * 8];
__device__ __align__(16) unsigned g_XL[(INF / 2) * 8];

// Fused: zero the output AND split x into fp16 hi/lo slabs.
__global__ void prep_zero(const float* __restrict__ x, float4* __restrict__ out4, int nout4) {
    int i = blockIdx.x * blockDim.x + threadIdx.x;
    if (i < (INF / 2) * 8) {
        int k2 = i >> 3, n = i & 7;
        float f0 = x[n * INF + 2 * k2];
        float f1 = x[n * INF + 2 * k2 + 1];
        __half h0 = __float2half_rn(f0), h1 = __float2half_rn(f1);
        __half l0 = __float2half_rn(f0 - __half2float(h0));
        __half l1 = __float2half_rn(f1 - __half2float(h1));
        __half2 H = __halves2half2(h0, h1), L = __halves2half2(l0, l1);
        g_XH[i] = *reinterpret_cast<unsigned*>(&H);
        g_XL[i] = *reinterpret_cast<unsigned*>(&L);
    }
    if (i < nout4) out4[i] = make_float4(0.f, 0.f, 0.f, 0.f);
}

// Dequant one packed byte (one int32, two nibbles) -> half2 (n_lo-8, n_hi-8), exact.
__device__ __forceinline__ unsigned dq(unsigned v) {
    unsigned t = ((v | (v << 12)) & 0x000F000Fu) | 0x64006400u;  // fp16 (1024+n)
    unsigned c = 0xE408E408u;                                    // half2(-1032)
    __half2 h = __hadd2(*reinterpret_cast<__half2*>(&t),
                        *reinterpret_cast<__half2*>(&c));        // n-8 (Sterbenz exact)
    return *reinterpret_cast<unsigned*>(&h);
}

__device__ __forceinline__ void mma16816(float& d0, float& d1, float& d2, float& d3,
                                         unsigned a0, unsigned a1, unsigned a2, unsigned a3,
                                         unsigned b0, unsigned b1) {
    asm volatile(
        "mma.sync.aligned.m16n8k16.row.col.f32.f16.f16.f32 "
        "{%0,%1,%2,%3},{%4,%5,%6,%7},{%8,%9},{%0,%1,%2,%3};"
        : "+f"(d0), "+f"(d1), "+f"(d2), "+f"(d3)
        : "r"(a0), "r"(a1), "r"(a2), "r"(a3), "r"(b0), "r"(b1));
}

__device__ __forceinline__ void cpa16(void* smem, const void* gmem) {
    unsigned s = (unsigned)__cvta_generic_to_shared(smem);
    asm volatile("cp.async.cg.shared.global [%0], [%1], 16;" :: "r"(s), "l"(gmem));
}

__global__ __launch_bounds__(128, 4)
void qlin_kernel(const int*   __restrict__ packed,
                 const float* __restrict__ scales,
                 float*       __restrict__ out) {
    __shared__ __align__(16) unsigned Wsm[ROWS * WSTRIDE];      // 33792 B
    __shared__ __align__(16) unsigned xhs[(KCTA / 2) * 8];      // 4096 B
    __shared__ __align__(16) unsigned xls[(KCTA / 2) * 8];      // 4096 B
    __shared__ float ssm[ROWS * 9];                             // 2304 B

    const int tid  = threadIdx.x;
    const int lane = tid & 31, warp = tid >> 5;
    const int gid  = lane >> 2, tg = lane & 3;
    const int rowbase = blockIdx.x * ROWS;
    const int kbase   = blockIdx.y * KCTA;
    const int kb2     = kbase >> 1;

    // ── W fill via cp.async: 64 rows x 128 words = 2048 int4; 16 per thread.
    {
        const int* pg = packed + (size_t)rowbase * (INF / 2) + kb2;
        #pragma unroll
        for (int p = 0; p < 16; p++) {
            int idx = p * 128 + tid;
            int row = idx >> 5, q = idx & 31;            // 32 int4 per row
            cpa16(&Wsm[row * WSTRIDE + q * 4], pg + (size_t)row * (INF / 2) + q * 4);
        }
    }
    // ── x fill via cp.async: 1024 words per slab = 256 int4 each; 2 per thread.
    {
        const int4* gh = reinterpret_cast<const int4*>(g_XH + kb2 * 8);
        const int4* gl = reinterpret_cast<const int4*>(g_XL + kb2 * 8);
        cpa16(reinterpret_cast<int4*>(xhs) + tid,       gh + tid);
        cpa16(reinterpret_cast<int4*>(xhs) + 128 + tid, gh + 128 + tid);
        cpa16(reinterpret_cast<int4*>(xls) + tid,       gl + tid);
        cpa16(reinterpret_cast<int4*>(xls) + 128 + tid, gl + 128 + tid);
    }
    // ── scales fill: 64 rows x 8 blocks, f32, stride 9 (conflict-free on compute).
    if (tid < ROWS) {
        const float* sg = scales + (size_t)(rowbase + tid) * (INF / 32) + (kbase >> 5);
        float4 a = *reinterpret_cast<const float4*>(sg);
        float4 b = *reinterpret_cast<const float4*>(sg + 4);
        float* d = &ssm[tid * 9];
        d[0] = a.x; d[1] = a.y; d[2] = a.z; d[3] = a.w;
        d[4] = b.x; d[5] = b.y; d[6] = b.z; d[7] = b.w;
    }
    asm volatile("cp.async.commit_group;\ncp.async.wait_group 0;" ::: "memory");
    __syncthreads();

    const int r0 = warp * 16 + gid;                 // rows r0 and r0+8
    const unsigned* wr0 = &Wsm[r0 * WSTRIDE];
    const unsigned* wr8 = wr0 + 8 * WSTRIDE;

    float acc0 = 0.f, acc1 = 0.f, acc2 = 0.f, acc3 = 0.f;

    #pragma unroll
    for (int blk = 0; blk < 8; blk++) {             // q4 block = 32 cols = 2 k-tiles
        float t0 = 0.f, t1 = 0.f, t2 = 0.f, t3 = 0.f;
        #pragma unroll
        for (int u = 0; u < 2; u++) {
            const int t = blk * 2 + u;
            const int j = 8 * t + tg;               // word j -> cols (2j, 2j+1)
            unsigned a0 = dq(wr0[j]);
            unsigned a1 = dq(wr8[j]);
            unsigned a2 = dq(wr0[j + 4]);
            unsigned a3 = dq(wr8[j + 4]);
            unsigned bh0 = xhs[j * 8 + gid];
            unsigned bh1 = xhs[(j + 4) * 8 + gid];
            unsigned bl0 = xls[j * 8 + gid];
            unsigned bl1 = xls[(j + 4) * 8 + gid];
            mma16816(t0, t1, t2, t3, a0, a1, a2, a3, bh0, bh1);
            mma16816(t0, t1, t2, t3, a0, a1, a2, a3, bl0, bl1);
        }
        float s0 = ssm[r0 * 9 + blk];
        float s8 = ssm[(r0 + 8) * 9 + blk];
        acc0 = fmaf(s0, t0, acc0);
        acc1 = fmaf(s0, t1, acc1);
        acc2 = fmaf(s8, t2, acc2);
        acc3 = fmaf(s8, t3, acc3);
    }

    // ── Epilogue: D frag -> out[batch][row]; 4 atomics/lane, no reduction.
    const int gr0 = rowbase + r0, gr8 = gr0 + 8;
    atomicAdd(&out[(size_t)(2 * tg)     * OUTF + gr0], acc0);
    atomicAdd(&out[(size_t)(2 * tg + 1) * OUTF + gr0], acc1);
    atomicAdd(&out[(size_t)(2 * tg)     * OUTF + gr8], acc2);
    atomicAdd(&out[(size_t)(2 * tg + 1) * OUTF + gr8], acc3);
}

extern "C" void kernel_launch(void* const* d_in, const int* in_sizes, int n_in,
                              void* d_out, int out_size) {
    const float* x      = (const float*)d_in[0];
    const int*   packed = (const int*)d_in[1];
    const float* scales = (const float*)d_in[2];
    float*       out    = (float*)d_out;

    int nout4 = out_size / 4;                       // 22016 float4s
    int naux  = (INF / 2) * 8;                      // 16384 split items
    int nthr  = nout4 > naux ? nout4 : naux;
    prep_zero<<<(nthr + 255) / 256, 256>>>(x, (float4*)out, nout4);

    dim3 grid(GRID_X, GRID_Y);                      // (172, 16) = 2752 CTAs
    qlin_kernel<<<grid, 128>>>(packed, scales, out);
}